// round 12
// baseline (speedup 1.0000x reference)
#include <cuda_runtime.h>
#include <math.h>

#define Bsz 4
#define Ssz 2048
#define Dm  1024
#define DV  64
#define Mrows (Bsz * Ssz)   // 8192

// ---------------- scratch (device globals; no allocation allowed) ----------
__device__ float  g_Q [(size_t)Mrows * Dm];   // 32 MB
__device__ float  g_K [(size_t)Mrows * Dm];   // 32 MB
__device__ float  g_Vp[(size_t)Mrows * DV];   // 2 MB   V' = x @ Wc^T
__device__ float  g_Wc[DV * Dm];              // Wc = Wo @ Wv
__device__ float  g_Op[2][(size_t)Mrows * DV];// partial (unnormalized) O per kv-parity
__device__ float2 g_ml[2][Mrows];             // per-row (m, l) per kv-parity

// ---------------------------------------------------------------------------
// Wc[v][d] = sum_e Wo[v][e] * Wv[e][d]        (64 x 1024, tiny)
// grid (4, 64), 256 threads
// ---------------------------------------------------------------------------
__global__ void wc_kernel(const float* __restrict__ Wv, const float* __restrict__ Wo) {
    int d = blockIdx.x * 256 + threadIdx.x;   // 0..1023
    int v = blockIdx.y;                       // 0..63
    const float* wo = Wo + (size_t)v * Dm;
    float acc = 0.f;
#pragma unroll 8
    for (int e = 0; e < Dm; ++e)
        acc = fmaf(wo[e], Wv[(size_t)e * Dm + d], acc);
    g_Wc[v * Dm + d] = acc;
}

// ---------------------------------------------------------------------------
// Q / K projection: out[m][n] = sum_k x[m][k] * W[n][k]
// M=8192, N=1024, K=1024. Tile 128x128x16, 256 threads, 8x8 micro.
// grid (8, 64, 2): z=0 -> Wq->g_Q, z=1 -> Wk->g_K
// ---------------------------------------------------------------------------
#define GP 132  // padded row stride (floats) for 128-wide transposed tiles

__global__ void __launch_bounds__(256) qk_gemm_kernel(const float* __restrict__ x,
                                                      const float* __restrict__ Wq,
                                                      const float* __restrict__ Wk) {
    __shared__ float At[16 * GP];
    __shared__ float Bt[16 * GP];

    const float* W   = blockIdx.z ? Wk  : Wq;
    float*       out = blockIdx.z ? g_K : g_Q;
    int m0 = blockIdx.y * 128;
    int n0 = blockIdx.x * 128;
    int tid = threadIdx.x;
    int cr = tid >> 4;      // 0..15 : row group (8 rows)
    int cc = tid & 15;      // 0..15 : col group (8 cols)

    float acc[8][8];
#pragma unroll
    for (int i = 0; i < 8; ++i)
#pragma unroll
        for (int j = 0; j < 8; ++j) acc[i][j] = 0.f;

    for (int c = 0; c < 64; ++c) {
        int k0 = c * 16;
#pragma unroll
        for (int i = 0; i < 2; ++i) {
            int f = tid + i * 256;          // 0..511
            int r = f >> 2, sg = f & 3;     // r: 0..127, sg: 0..3 (4 float4 per row)
            float4 av = *(const float4*)(x + (size_t)(m0 + r) * Dm + k0 + sg * 4);
            At[(sg * 4 + 0) * GP + r] = av.x;
            At[(sg * 4 + 1) * GP + r] = av.y;
            At[(sg * 4 + 2) * GP + r] = av.z;
            At[(sg * 4 + 3) * GP + r] = av.w;
            float4 bv = *(const float4*)(W + (size_t)(n0 + r) * Dm + k0 + sg * 4);
            Bt[(sg * 4 + 0) * GP + r] = bv.x;
            Bt[(sg * 4 + 1) * GP + r] = bv.y;
            Bt[(sg * 4 + 2) * GP + r] = bv.z;
            Bt[(sg * 4 + 3) * GP + r] = bv.w;
        }
        __syncthreads();
#pragma unroll
        for (int kk = 0; kk < 16; ++kk) {
            float a[8], b[8];
            *(float4*)(a)     = *(const float4*)(At + kk * GP + cr * 8);
            *(float4*)(a + 4) = *(const float4*)(At + kk * GP + cr * 8 + 4);
            *(float4*)(b)     = *(const float4*)(Bt + kk * GP + cc * 8);
            *(float4*)(b + 4) = *(const float4*)(Bt + kk * GP + cc * 8 + 4);
#pragma unroll
            for (int i = 0; i < 8; ++i)
#pragma unroll
                for (int j = 0; j < 8; ++j)
                    acc[i][j] = fmaf(a[i], b[j], acc[i][j]);
        }
        __syncthreads();
    }

#pragma unroll
    for (int i = 0; i < 8; ++i) {
        size_t o = (size_t)(m0 + cr * 8 + i) * Dm + n0 + cc * 8;
        *(float4*)(out + o)     = make_float4(acc[i][0], acc[i][1], acc[i][2], acc[i][3]);
        *(float4*)(out + o + 4) = make_float4(acc[i][4], acc[i][5], acc[i][6], acc[i][7]);
    }
}

// ---------------------------------------------------------------------------
// V'[m][v] = sum_k x[m][k] * Wc[v][k]   M=8192, N=64, K=1024
// Tile 128x64x16, 256 threads (16 ty x 16 tx), micro 8x4. grid(64)
// ---------------------------------------------------------------------------
#define BP 68   // padded stride for 64-wide tiles

__global__ void __launch_bounds__(256) vp_gemm_kernel(const float* __restrict__ x) {
    __shared__ float At[16 * GP];
    __shared__ float Bt[16 * BP];

    int m0 = blockIdx.x * 128;
    int tid = threadIdx.x;
    int ty = tid >> 4;   // rows: ty*8 .. +7
    int tx = tid & 15;   // cols: tx*4 .. +3

    float acc[8][4];
#pragma unroll
    for (int i = 0; i < 8; ++i)
#pragma unroll
        for (int j = 0; j < 4; ++j) acc[i][j] = 0.f;

    for (int c = 0; c < 64; ++c) {
        int k0 = c * 16;
#pragma unroll
        for (int i = 0; i < 2; ++i) {
            int f = tid + i * 256;
            int r = f >> 2, sg = f & 3;
            float4 av = *(const float4*)(x + (size_t)(m0 + r) * Dm + k0 + sg * 4);
            At[(sg * 4 + 0) * GP + r] = av.x;
            At[(sg * 4 + 1) * GP + r] = av.y;
            At[(sg * 4 + 2) * GP + r] = av.z;
            At[(sg * 4 + 3) * GP + r] = av.w;
        }
        {   // Wc: 64 rows x 16 k = 256 float4, one per thread
            int r = tid >> 2, sg = tid & 3;
            float4 bv = *(const float4*)(g_Wc + (size_t)r * Dm + k0 + sg * 4);
            Bt[(sg * 4 + 0) * BP + r] = bv.x;
            Bt[(sg * 4 + 1) * BP + r] = bv.y;
            Bt[(sg * 4 + 2) * BP + r] = bv.z;
            Bt[(sg * 4 + 3) * BP + r] = bv.w;
        }
        __syncthreads();
#pragma unroll
        for (int kk = 0; kk < 16; ++kk) {
            float a[8], b[4];
            *(float4*)(a)     = *(const float4*)(At + kk * GP + ty * 8);
            *(float4*)(a + 4) = *(const float4*)(At + kk * GP + ty * 8 + 4);
            *(float4*)(b)     = *(const float4*)(Bt + kk * BP + tx * 4);
#pragma unroll
            for (int i = 0; i < 8; ++i)
#pragma unroll
                for (int j = 0; j < 4; ++j)
                    acc[i][j] = fmaf(a[i], b[j], acc[i][j]);
        }
        __syncthreads();
    }

#pragma unroll
    for (int i = 0; i < 8; ++i) {
        size_t o = (size_t)(m0 + ty * 8 + i) * DV + tx * 4;
        *(float4*)(g_Vp + o) = make_float4(acc[i][0], acc[i][1], acc[i][2], acc[i][3]);
    }
}

// ---------------------------------------------------------------------------
// Flash attention, causal, d_qk = 1024, d_v = 64.
// CTA = (qtile of 64 queries, batch, kv-parity). BN = 128 keys per kv tile.
// 256 threads: tx = tid&15 (S cols: 8 each / O cols: 4 each), ty = tid>>4 (rows: 4 each)
// Each parity CTA handles kv tiles t = par, par+2, ... and writes unnormalized
// partials (O~, m, l); merge_kernel combines the two parities.
// ---------------------------------------------------------------------------
#define QT_STR 68    // Qt [32][68]
#define KT_STR 132   // Kt [32][132]
#define PS_STR 132   // Ps [64][132]
#define VS_STR 68    // Vs [128][68]
#define ATTN_SMEM_FLOATS (32*QT_STR + 32*KT_STR + 64*PS_STR + 128*VS_STR)

__global__ void __launch_bounds__(256) attn_kernel() {
    extern __shared__ float sm[];
    float* Qt = sm;                     // [32][68]
    float* Kt = Qt + 32 * QT_STR;       // [32][132]
    float* Ps = Kt + 32 * KT_STR;       // [64][132]
    float* Vs = Ps + 64 * PS_STR;       // [128][68]

    int qt  = blockIdx.x;       // 0..31
    int b   = blockIdx.y;       // 0..3
    int par = blockIdx.z;       // 0..1
    int q0  = qt * 64;

    const float* Qg = g_Q  + ((size_t)b * Ssz + q0) * Dm;
    const float* Kg = g_K  + (size_t)b * Ssz * Dm;
    const float* Vg = g_Vp + (size_t)b * Ssz * DV;

    int tid = threadIdx.x;
    int tx = tid & 15;
    int ty = tid >> 4;

    float m_i[4], l_i[4], O[4][4];
#pragma unroll
    for (int i = 0; i < 4; ++i) {
        m_i[i] = -1e30f; l_i[i] = 0.f;
#pragma unroll
        for (int j = 0; j < 4; ++j) O[i][j] = 0.f;
    }

    int nkv = qt / 2 + 1;   // kv tiles of 128 keys needed for this qtile

    for (int t = par; t < nkv; t += 2) {
        int k0 = t * 128;

        // ---- S = Q @ K^T  (D=1024 in chunks of 32) ----
        float acc[4][8];
#pragma unroll
        for (int i = 0; i < 4; ++i)
#pragma unroll
            for (int j = 0; j < 8; ++j) acc[i][j] = 0.f;

        for (int c = 0; c < 32; ++c) {
            int c0 = c * 32;
#pragma unroll
            for (int i = 0; i < 2; ++i) {          // Q chunk: 64x32 = 512 float4
                int f = tid + i * 256;
                int r = f >> 3, sg = f & 7;
                float4 v = *(const float4*)(Qg + (size_t)r * Dm + c0 + sg * 4);
                Qt[(sg * 4 + 0) * QT_STR + r] = v.x;
                Qt[(sg * 4 + 1) * QT_STR + r] = v.y;
                Qt[(sg * 4 + 2) * QT_STR + r] = v.z;
                Qt[(sg * 4 + 3) * QT_STR + r] = v.w;
            }
#pragma unroll
            for (int i = 0; i < 4; ++i) {          // K chunk: 128x32 = 1024 float4
                int f = tid + i * 256;
                int r = f >> 3, sg = f & 7;
                float4 v = *(const float4*)(Kg + (size_t)(k0 + r) * Dm + c0 + sg * 4);
                Kt[(sg * 4 + 0) * KT_STR + r] = v.x;
                Kt[(sg * 4 + 1) * KT_STR + r] = v.y;
                Kt[(sg * 4 + 2) * KT_STR + r] = v.z;
                Kt[(sg * 4 + 3) * KT_STR + r] = v.w;
            }
            __syncthreads();
#pragma unroll
            for (int kk = 0; kk < 32; ++kk) {
                float a[4], bb[8];
                *(float4*)(a)      = *(const float4*)(Qt + kk * QT_STR + ty * 4);
                *(float4*)(bb)     = *(const float4*)(Kt + kk * KT_STR + tx * 8);
                *(float4*)(bb + 4) = *(const float4*)(Kt + kk * KT_STR + tx * 8 + 4);
#pragma unroll
                for (int i = 0; i < 4; ++i)
#pragma unroll
                    for (int j = 0; j < 8; ++j)
                        acc[i][j] = fmaf(a[i], bb[j], acc[i][j]);
            }
            __syncthreads();
        }

        // ---- online softmax update (mask -> scale -> exp) ----
#pragma unroll
        for (int i = 0; i < 4; ++i) {
            int q = q0 + ty * 4 + i;
            float mt = -1e30f;
#pragma unroll
            for (int j = 0; j < 8; ++j) {
                int k = k0 + tx * 8 + j;
                float s = (k <= q) ? acc[i][j] * 0.03125f : -1e30f;  // 1/sqrt(1024)
                acc[i][j] = s;
                mt = fmaxf(mt, s);
            }
            mt = fmaxf(mt, __shfl_xor_sync(0xffffffffu, mt, 1));
            mt = fmaxf(mt, __shfl_xor_sync(0xffffffffu, mt, 2));
            mt = fmaxf(mt, __shfl_xor_sync(0xffffffffu, mt, 4));
            mt = fmaxf(mt, __shfl_xor_sync(0xffffffffu, mt, 8));

            float mn = fmaxf(m_i[i], mt);
            float corr = __expf(m_i[i] - mn);
            m_i[i] = mn;

            float rs = 0.f;
#pragma unroll
            for (int j = 0; j < 8; ++j) {
                float p = __expf(acc[i][j] - mn);
                acc[i][j] = p;
                rs += p;
            }
            rs += __shfl_xor_sync(0xffffffffu, rs, 1);
            rs += __shfl_xor_sync(0xffffffffu, rs, 2);
            rs += __shfl_xor_sync(0xffffffffu, rs, 4);
            rs += __shfl_xor_sync(0xffffffffu, rs, 8);

            l_i[i] = l_i[i] * corr + rs;
            O[i][0] *= corr; O[i][1] *= corr; O[i][2] *= corr; O[i][3] *= corr;
        }

        // ---- stage P to smem, load V' tile ----
#pragma unroll
        for (int i = 0; i < 4; ++i) {
            *(float4*)(Ps + (ty * 4 + i) * PS_STR + tx * 8) =
                make_float4(acc[i][0], acc[i][1], acc[i][2], acc[i][3]);
            *(float4*)(Ps + (ty * 4 + i) * PS_STR + tx * 8 + 4) =
                make_float4(acc[i][4], acc[i][5], acc[i][6], acc[i][7]);
        }
#pragma unroll
        for (int i = 0; i < 8; ++i) {              // V': 128x64 = 2048 float4
            int f = tid + i * 256;
            int r = f >> 4, sg = f & 15;
            *(float4*)(Vs + r * VS_STR + sg * 4) =
                *(const float4*)(Vg + (size_t)(k0 + r) * DV + sg * 4);
        }
        __syncthreads();

        // ---- O += P @ V' ----
#pragma unroll 2
        for (int k = 0; k < 128; ++k) {
            float4 v = *(const float4*)(Vs + k * VS_STR + tx * 4);
#pragma unroll
            for (int i = 0; i < 4; ++i) {
                float p = Ps[(ty * 4 + i) * PS_STR + k];
                O[i][0] = fmaf(p, v.x, O[i][0]);
                O[i][1] = fmaf(p, v.y, O[i][1]);
                O[i][2] = fmaf(p, v.z, O[i][2]);
                O[i][3] = fmaf(p, v.w, O[i][3]);
            }
        }
        __syncthreads();
    }

    // ---- write unnormalized partial + (m, l) ----
    float* Op = g_Op[par];
#pragma unroll
    for (int i = 0; i < 4; ++i) {
        size_t row = (size_t)b * Ssz + q0 + ty * 4 + i;
        *(float4*)(Op + row * DV + tx * 4) = make_float4(O[i][0], O[i][1], O[i][2], O[i][3]);
        if (tx == 0) g_ml[par][row] = make_float2(m_i[i], l_i[i]);
    }
}

// ---------------------------------------------------------------------------
// Merge the two kv-parity partials and normalize.
// grid 512 x 256 : one thread per (row, 4-col group) => 8192 * 16 threads
// ---------------------------------------------------------------------------
__global__ void merge_kernel(float* __restrict__ out) {
    int idx = blockIdx.x * 256 + threadIdx.x;   // 0..131071
    int row = idx >> 4;
    int cg  = (idx & 15) * 4;

    float2 ml0 = g_ml[0][row];
    float2 ml1 = g_ml[1][row];
    float M  = fmaxf(ml0.x, ml1.x);
    float e0 = __expf(ml0.x - M);
    float e1 = __expf(ml1.x - M);
    float inv = 1.0f / (ml0.y * e0 + ml1.y * e1);

    float4 o0 = *(const float4*)(g_Op[0] + (size_t)row * DV + cg);
    float4 o1 = *(const float4*)(g_Op[1] + (size_t)row * DV + cg);
    float4 r;
    r.x = (o0.x * e0 + o1.x * e1) * inv;
    r.y = (o0.y * e0 + o1.y * e1) * inv;
    r.z = (o0.z * e0 + o1.z * e1) * inv;
    r.w = (o0.w * e0 + o1.w * e1) * inv;
    *(float4*)(out + (size_t)row * DV + cg) = r;
}

// ---------------------------------------------------------------------------
extern "C" void kernel_launch(void* const* d_in, const int* in_sizes, int n_in,
                              void* d_out, int out_size) {
    (void)in_sizes; (void)n_in; (void)out_size;
    const float* x  = (const float*)d_in[0];
    const float* Wq = (const float*)d_in[1];
    const float* Wk = (const float*)d_in[2];
    const float* Wv = (const float*)d_in[3];
    const float* Wo = (const float*)d_in[4];
    float* out = (float*)d_out;

    const int attn_smem = ATTN_SMEM_FLOATS * (int)sizeof(float);  // ~94 KB
    cudaFuncSetAttribute(attn_kernel, cudaFuncAttributeMaxDynamicSharedMemorySize, attn_smem);

    wc_kernel     <<<dim3(4, 64),      256>>>(Wv, Wo);
    qk_gemm_kernel<<<dim3(8, 64, 2),   256>>>(x, Wq, Wk);
    vp_gemm_kernel<<<64,               256>>>(x);
    attn_kernel   <<<dim3(32, Bsz, 2), 256, attn_smem>>>();
    merge_kernel  <<<512,              256>>>(out);
}

// round 13
// speedup vs baseline: 1.0010x; 1.0010x over previous
#include <cuda_runtime.h>
#include <math.h>

#define Bsz 4
#define Ssz 2048
#define Dm  1024
#define DV  64
#define Mrows (Bsz * Ssz)   // 8192

// ---------------- scratch (device globals; no allocation allowed) ----------
__device__ float  g_Q [(size_t)Mrows * Dm];   // 32 MB
__device__ float  g_K [(size_t)Mrows * Dm];   // 32 MB
__device__ float  g_Vp[(size_t)Mrows * DV];   // 2 MB   V' = x @ Wc^T
__device__ float  g_Wc[DV * Dm];              // Wc = Wo @ Wv
__device__ float  g_Op[2][(size_t)Mrows * DV];// partial (unnormalized) O per kv-parity
__device__ float2 g_ml[2][Mrows];             // per-row (m, l) per kv-parity

// ---------------------------------------------------------------------------
// Wc[v][d] = sum_e Wo[v][e] * Wv[e][d]        (64 x 1024, tiny)
// grid (4, 64), 256 threads
// ---------------------------------------------------------------------------
__global__ void wc_kernel(const float* __restrict__ Wv, const float* __restrict__ Wo) {
    int d = blockIdx.x * 256 + threadIdx.x;   // 0..1023
    int v = blockIdx.y;                       // 0..63
    const float* wo = Wo + (size_t)v * Dm;
    float acc = 0.f;
#pragma unroll 8
    for (int e = 0; e < Dm; ++e)
        acc = fmaf(wo[e], Wv[(size_t)e * Dm + d], acc);
    g_Wc[v * Dm + d] = acc;
}

// ---------------------------------------------------------------------------
// Q / K projection: out[m][n] = sum_k x[m][k] * W[n][k]
// M=8192, N=1024, K=1024. Tile 128x128x16, 256 threads, 8x8 micro.
// grid (8, 64, 2): z=0 -> Wq->g_Q, z=1 -> Wk->g_K
// ---------------------------------------------------------------------------
#define GP 132  // padded row stride (floats) for 128-wide transposed tiles

__global__ void __launch_bounds__(256) qk_gemm_kernel(const float* __restrict__ x,
                                                      const float* __restrict__ Wq,
                                                      const float* __restrict__ Wk) {
    __shared__ float At[16 * GP];
    __shared__ float Bt[16 * GP];

    const float* W   = blockIdx.z ? Wk  : Wq;
    float*       out = blockIdx.z ? g_K : g_Q;
    int m0 = blockIdx.y * 128;
    int n0 = blockIdx.x * 128;
    int tid = threadIdx.x;
    int cr = tid >> 4;      // 0..15 : row group (8 rows)
    int cc = tid & 15;      // 0..15 : col group (8 cols)

    float acc[8][8];
#pragma unroll
    for (int i = 0; i < 8; ++i)
#pragma unroll
        for (int j = 0; j < 8; ++j) acc[i][j] = 0.f;

    for (int c = 0; c < 64; ++c) {
        int k0 = c * 16;
#pragma unroll
        for (int i = 0; i < 2; ++i) {
            int f = tid + i * 256;          // 0..511
            int r = f >> 2, sg = f & 3;     // r: 0..127, sg: 0..3 (4 float4 per row)
            float4 av = *(const float4*)(x + (size_t)(m0 + r) * Dm + k0 + sg * 4);
            At[(sg * 4 + 0) * GP + r] = av.x;
            At[(sg * 4 + 1) * GP + r] = av.y;
            At[(sg * 4 + 2) * GP + r] = av.z;
            At[(sg * 4 + 3) * GP + r] = av.w;
            float4 bv = *(const float4*)(W + (size_t)(n0 + r) * Dm + k0 + sg * 4);
            Bt[(sg * 4 + 0) * GP + r] = bv.x;
            Bt[(sg * 4 + 1) * GP + r] = bv.y;
            Bt[(sg * 4 + 2) * GP + r] = bv.z;
            Bt[(sg * 4 + 3) * GP + r] = bv.w;
        }
        __syncthreads();
#pragma unroll
        for (int kk = 0; kk < 16; ++kk) {
            float a[8], b[8];
            *(float4*)(a)     = *(const float4*)(At + kk * GP + cr * 8);
            *(float4*)(a + 4) = *(const float4*)(At + kk * GP + cr * 8 + 4);
            *(float4*)(b)     = *(const float4*)(Bt + kk * GP + cc * 8);
            *(float4*)(b + 4) = *(const float4*)(Bt + kk * GP + cc * 8 + 4);
#pragma unroll
            for (int i = 0; i < 8; ++i)
#pragma unroll
                for (int j = 0; j < 8; ++j)
                    acc[i][j] = fmaf(a[i], b[j], acc[i][j]);
        }
        __syncthreads();
    }

#pragma unroll
    for (int i = 0; i < 8; ++i) {
        size_t o = (size_t)(m0 + cr * 8 + i) * Dm + n0 + cc * 8;
        *(float4*)(out + o)     = make_float4(acc[i][0], acc[i][1], acc[i][2], acc[i][3]);
        *(float4*)(out + o + 4) = make_float4(acc[i][4], acc[i][5], acc[i][6], acc[i][7]);
    }
}

// ---------------------------------------------------------------------------
// V'[m][v] = sum_k x[m][k] * Wc[v][k]   M=8192, N=64, K=1024
// Tile 128x64x16, 256 threads (16 ty x 16 tx), micro 8x4. grid(64)
// ---------------------------------------------------------------------------
#define BP 68   // padded stride for 64-wide tiles

__global__ void __launch_bounds__(256) vp_gemm_kernel(const float* __restrict__ x) {
    __shared__ float At[16 * GP];
    __shared__ float Bt[16 * BP];

    int m0 = blockIdx.x * 128;
    int tid = threadIdx.x;
    int ty = tid >> 4;   // rows: ty*8 .. +7
    int tx = tid & 15;   // cols: tx*4 .. +3

    float acc[8][4];
#pragma unroll
    for (int i = 0; i < 8; ++i)
#pragma unroll
        for (int j = 0; j < 4; ++j) acc[i][j] = 0.f;

    for (int c = 0; c < 64; ++c) {
        int k0 = c * 16;
#pragma unroll
        for (int i = 0; i < 2; ++i) {
            int f = tid + i * 256;
            int r = f >> 2, sg = f & 3;
            float4 av = *(const float4*)(x + (size_t)(m0 + r) * Dm + k0 + sg * 4);
            At[(sg * 4 + 0) * GP + r] = av.x;
            At[(sg * 4 + 1) * GP + r] = av.y;
            At[(sg * 4 + 2) * GP + r] = av.z;
            At[(sg * 4 + 3) * GP + r] = av.w;
        }
        {   // Wc: 64 rows x 16 k = 256 float4, one per thread
            int r = tid >> 2, sg = tid & 3;
            float4 bv = *(const float4*)(g_Wc + (size_t)r * Dm + k0 + sg * 4);
            Bt[(sg * 4 + 0) * BP + r] = bv.x;
            Bt[(sg * 4 + 1) * BP + r] = bv.y;
            Bt[(sg * 4 + 2) * BP + r] = bv.z;
            Bt[(sg * 4 + 3) * BP + r] = bv.w;
        }
        __syncthreads();
#pragma unroll
        for (int kk = 0; kk < 16; ++kk) {
            float a[8], b[4];
            *(float4*)(a)     = *(const float4*)(At + kk * GP + ty * 8);
            *(float4*)(a + 4) = *(const float4*)(At + kk * GP + ty * 8 + 4);
            *(float4*)(b)     = *(const float4*)(Bt + kk * BP + tx * 4);
#pragma unroll
            for (int i = 0; i < 8; ++i)
#pragma unroll
                for (int j = 0; j < 4; ++j)
                    acc[i][j] = fmaf(a[i], b[j], acc[i][j]);
        }
        __syncthreads();
    }

#pragma unroll
    for (int i = 0; i < 8; ++i) {
        size_t o = (size_t)(m0 + ty * 8 + i) * DV + tx * 4;
        *(float4*)(g_Vp + o) = make_float4(acc[i][0], acc[i][1], acc[i][2], acc[i][3]);
    }
}

// ---------------------------------------------------------------------------
// Flash attention, causal, d_qk = 1024, d_v = 64.
// CTA = (qtile of 64 queries, batch, kv-parity). BN = 128 keys per kv tile.
// 256 threads: tx = tid&15 (S cols: 8 each / O cols: 4 each), ty = tid>>4 (rows: 4 each)
// Each parity CTA handles kv tiles t = par, par+2, ... and writes unnormalized
// partials (O~, m, l); merge_kernel combines the two parities.
// ---------------------------------------------------------------------------
#define QT_STR 68    // Qt [32][68]
#define KT_STR 132   // Kt [32][132]
#define PS_STR 132   // Ps [64][132]
#define VS_STR 68    // Vs [128][68]
#define ATTN_SMEM_FLOATS (32*QT_STR + 32*KT_STR + 64*PS_STR + 128*VS_STR)

__global__ void __launch_bounds__(256) attn_kernel() {
    extern __shared__ float sm[];
    float* Qt = sm;                     // [32][68]
    float* Kt = Qt + 32 * QT_STR;       // [32][132]
    float* Ps = Kt + 32 * KT_STR;       // [64][132]
    float* Vs = Ps + 64 * PS_STR;       // [128][68]

    int qt  = blockIdx.x;       // 0..31
    int b   = blockIdx.y;       // 0..3
    int par = blockIdx.z;       // 0..1
    int q0  = qt * 64;

    const float* Qg = g_Q  + ((size_t)b * Ssz + q0) * Dm;
    const float* Kg = g_K  + (size_t)b * Ssz * Dm;
    const float* Vg = g_Vp + (size_t)b * Ssz * DV;

    int tid = threadIdx.x;
    int tx = tid & 15;
    int ty = tid >> 4;

    float m_i[4], l_i[4], O[4][4];
#pragma unroll
    for (int i = 0; i < 4; ++i) {
        m_i[i] = -1e30f; l_i[i] = 0.f;
#pragma unroll
        for (int j = 0; j < 4; ++j) O[i][j] = 0.f;
    }

    int nkv = qt / 2 + 1;   // kv tiles of 128 keys needed for this qtile

    for (int t = par; t < nkv; t += 2) {
        int k0 = t * 128;

        // ---- S = Q @ K^T  (D=1024 in chunks of 32) ----
        float acc[4][8];
#pragma unroll
        for (int i = 0; i < 4; ++i)
#pragma unroll
            for (int j = 0; j < 8; ++j) acc[i][j] = 0.f;

        for (int c = 0; c < 32; ++c) {
            int c0 = c * 32;
#pragma unroll
            for (int i = 0; i < 2; ++i) {          // Q chunk: 64x32 = 512 float4
                int f = tid + i * 256;
                int r = f >> 3, sg = f & 7;
                float4 v = *(const float4*)(Qg + (size_t)r * Dm + c0 + sg * 4);
                Qt[(sg * 4 + 0) * QT_STR + r] = v.x;
                Qt[(sg * 4 + 1) * QT_STR + r] = v.y;
                Qt[(sg * 4 + 2) * QT_STR + r] = v.z;
                Qt[(sg * 4 + 3) * QT_STR + r] = v.w;
            }
#pragma unroll
            for (int i = 0; i < 4; ++i) {          // K chunk: 128x32 = 1024 float4
                int f = tid + i * 256;
                int r = f >> 3, sg = f & 7;
                float4 v = *(const float4*)(Kg + (size_t)(k0 + r) * Dm + c0 + sg * 4);
                Kt[(sg * 4 + 0) * KT_STR + r] = v.x;
                Kt[(sg * 4 + 1) * KT_STR + r] = v.y;
                Kt[(sg * 4 + 2) * KT_STR + r] = v.z;
                Kt[(sg * 4 + 3) * KT_STR + r] = v.w;
            }
            __syncthreads();
#pragma unroll
            for (int kk = 0; kk < 32; ++kk) {
                float a[4], bb[8];
                *(float4*)(a)      = *(const float4*)(Qt + kk * QT_STR + ty * 4);
                *(float4*)(bb)     = *(const float4*)(Kt + kk * KT_STR + tx * 8);
                *(float4*)(bb + 4) = *(const float4*)(Kt + kk * KT_STR + tx * 8 + 4);
#pragma unroll
                for (int i = 0; i < 4; ++i)
#pragma unroll
                    for (int j = 0; j < 8; ++j)
                        acc[i][j] = fmaf(a[i], bb[j], acc[i][j]);
            }
            __syncthreads();
        }

        // ---- online softmax update (mask -> scale -> exp) ----
#pragma unroll
        for (int i = 0; i < 4; ++i) {
            int q = q0 + ty * 4 + i;
            float mt = -1e30f;
#pragma unroll
            for (int j = 0; j < 8; ++j) {
                int k = k0 + tx * 8 + j;
                float s = (k <= q) ? acc[i][j] * 0.03125f : -1e30f;  // 1/sqrt(1024)
                acc[i][j] = s;
                mt = fmaxf(mt, s);
            }
            mt = fmaxf(mt, __shfl_xor_sync(0xffffffffu, mt, 1));
            mt = fmaxf(mt, __shfl_xor_sync(0xffffffffu, mt, 2));
            mt = fmaxf(mt, __shfl_xor_sync(0xffffffffu, mt, 4));
            mt = fmaxf(mt, __shfl_xor_sync(0xffffffffu, mt, 8));

            float mn = fmaxf(m_i[i], mt);
            float corr = __expf(m_i[i] - mn);
            m_i[i] = mn;

            float rs = 0.f;
#pragma unroll
            for (int j = 0; j < 8; ++j) {
                float p = __expf(acc[i][j] - mn);
                acc[i][j] = p;
                rs += p;
            }
            rs += __shfl_xor_sync(0xffffffffu, rs, 1);
            rs += __shfl_xor_sync(0xffffffffu, rs, 2);
            rs += __shfl_xor_sync(0xffffffffu, rs, 4);
            rs += __shfl_xor_sync(0xffffffffu, rs, 8);

            l_i[i] = l_i[i] * corr + rs;
            O[i][0] *= corr; O[i][1] *= corr; O[i][2] *= corr; O[i][3] *= corr;
        }

        // ---- stage P to smem, load V' tile ----
#pragma unroll
        for (int i = 0; i < 4; ++i) {
            *(float4*)(Ps + (ty * 4 + i) * PS_STR + tx * 8) =
                make_float4(acc[i][0], acc[i][1], acc[i][2], acc[i][3]);
            *(float4*)(Ps + (ty * 4 + i) * PS_STR + tx * 8 + 4) =
                make_float4(acc[i][4], acc[i][5], acc[i][6], acc[i][7]);
        }
#pragma unroll
        for (int i = 0; i < 8; ++i) {              // V': 128x64 = 2048 float4
            int f = tid + i * 256;
            int r = f >> 4, sg = f & 15;
            *(float4*)(Vs + r * VS_STR + sg * 4) =
                *(const float4*)(Vg + (size_t)(k0 + r) * DV + sg * 4);
        }
        __syncthreads();

        // ---- O += P @ V' ----
#pragma unroll 2
        for (int k = 0; k < 128; ++k) {
            float4 v = *(const float4*)(Vs + k * VS_STR + tx * 4);
#pragma unroll
            for (int i = 0; i < 4; ++i) {
                float p = Ps[(ty * 4 + i) * PS_STR + k];
                O[i][0] = fmaf(p, v.x, O[i][0]);
                O[i][1] = fmaf(p, v.y, O[i][1]);
                O[i][2] = fmaf(p, v.z, O[i][2]);
                O[i][3] = fmaf(p, v.w, O[i][3]);
            }
        }
        __syncthreads();
    }

    // ---- write unnormalized partial + (m, l) ----
    float* Op = g_Op[par];
#pragma unroll
    for (int i = 0; i < 4; ++i) {
        size_t row = (size_t)b * Ssz + q0 + ty * 4 + i;
        *(float4*)(Op + row * DV + tx * 4) = make_float4(O[i][0], O[i][1], O[i][2], O[i][3]);
        if (tx == 0) g_ml[par][row] = make_float2(m_i[i], l_i[i]);
    }
}

// ---------------------------------------------------------------------------
// Merge the two kv-parity partials and normalize.
// grid 512 x 256 : one thread per (row, 4-col group) => 8192 * 16 threads
// ---------------------------------------------------------------------------
__global__ void merge_kernel(float* __restrict__ out) {
    int idx = blockIdx.x * 256 + threadIdx.x;   // 0..131071
    int row = idx >> 4;
    int cg  = (idx & 15) * 4;

    float2 ml0 = g_ml[0][row];
    float2 ml1 = g_ml[1][row];
    float M  = fmaxf(ml0.x, ml1.x);
    float e0 = __expf(ml0.x - M);
    float e1 = __expf(ml1.x - M);
    float inv = 1.0f / (ml0.y * e0 + ml1.y * e1);

    float4 o0 = *(const float4*)(g_Op[0] + (size_t)row * DV + cg);
    float4 o1 = *(const float4*)(g_Op[1] + (size_t)row * DV + cg);
    float4 r;
    r.x = (o0.x * e0 + o1.x * e1) * inv;
    r.y = (o0.y * e0 + o1.y * e1) * inv;
    r.z = (o0.z * e0 + o1.z * e1) * inv;
    r.w = (o0.w * e0 + o1.w * e1) * inv;
    *(float4*)(out + (size_t)row * DV + cg) = r;
}

// ---------------------------------------------------------------------------
extern "C" void kernel_launch(void* const* d_in, const int* in_sizes, int n_in,
                              void* d_out, int out_size) {
    (void)in_sizes; (void)n_in; (void)out_size;
    const float* x  = (const float*)d_in[0];
    const float* Wq = (const float*)d_in[1];
    const float* Wk = (const float*)d_in[2];
    const float* Wv = (const float*)d_in[3];
    const float* Wo = (const float*)d_in[4];
    float* out = (float*)d_out;

    const int attn_smem = ATTN_SMEM_FLOATS * (int)sizeof(float);  // ~94 KB
    cudaFuncSetAttribute(attn_kernel, cudaFuncAttributeMaxDynamicSharedMemorySize, attn_smem);

    wc_kernel     <<<dim3(4, 64),      256>>>(Wv, Wo);
    qk_gemm_kernel<<<dim3(8, 64, 2),   256>>>(x, Wq, Wk);
    vp_gemm_kernel<<<64,               256>>>(x);
    attn_kernel   <<<dim3(32, Bsz, 2), 256, attn_smem>>>();
    merge_kernel  <<<512,              256>>>(out);
}